// round 2
// baseline (speedup 1.0000x reference)
#include <cuda_runtime.h>
#include <cuda_bf16.h>

#define NN 50000
#define EE 600000

// ---------------- device scratch (no allocations allowed) ----------------
__device__ __align__(16) float g_AB[NN * 128];    // [A | B] table for edge MLP
__device__ __align__(16) float g_ew[EE];          // edge weights
__device__ __align__(16) float g_deg[NN];
__device__ __align__(16) float g_dinv[NN];
__device__ __align__(16) float g_xl[NN * 128];    // x @ W^T (per conv)
__device__ __align__(16) float g_agg[NN * 128];   // scatter accumulator
__device__ __align__(16) float g_x1[NN * 128];    // relu output / activations
__device__ __align__(16) float g_WTp[128 * 128];  // k-major weights
__device__ __align__(16) float g_WT1[128 * 128];
__device__ __align__(16) float g_WT2[128 * 128];
__device__ __align__(16) int   g_src[EE];
__device__ __align__(16) int   g_dst[EE];

// ---------------- edge index conversion (dtype-robust) ----------------
// edge_index may be int32 (JAX x64 disabled) or int64. For int64, values are
// < 50000 so every high 32-bit word is 0. Probe 64 consecutive odd words: all
// zero -> int64 layout; otherwise int32.
__global__ void convert_edges(const int* __restrict__ raw) {
    bool is64 = true;
    #pragma unroll
    for (int i = 1; i < 128; i += 2)
        if (raw[i] != 0) { is64 = false; break; }
    int e = blockIdx.x * blockDim.x + threadIdx.x;
    if (e >= EE) return;
    if (is64) {
        g_src[e] = raw[2 * e];
        g_dst[e] = raw[2 * (EE + e)];
    } else {
        g_src[e] = raw[e];
        g_dst[e] = raw[EE + e];
    }
}

// ---------------- weight prep: build k-major 128x128 weights ----------------
__global__ void prep_weights(const float* __restrict__ W_p1,
                             const float* __restrict__ W1,
                             const float* __restrict__ W2) {
    for (int idx = threadIdx.x; idx < 128 * 128; idx += blockDim.x) {
        int k = idx >> 7;
        int j = idx & 127;
        g_WT1[idx] = W1[j * 128 + k];
        g_WT2[idx] = W2[j * 128 + k];
        // cols 0..63 -> W_p1a (first 128 inputs), 64..127 -> W_p1b (second 128)
        g_WTp[idx] = (j < 64) ? W_p1[j * 256 + k] : W_p1[(j - 64) * 256 + 128 + k];
    }
}

__global__ void init_deg() {
    int i = blockIdx.x * blockDim.x + threadIdx.x;
    if (i < NN) g_deg[i] = 1.0f;  // self-loop weight
}

// ---------------- register-tiled SGEMM: Y[M,128] = X[M,128] @ WT ----------------
// WT is k-major: WT[k*128 + j]. Block = 256 threads, tile 64 rows x 128 cols.
__global__ void gemm128(const float* __restrict__ X, const float* __restrict__ WT,
                        float* __restrict__ Y, int M) {
    extern __shared__ float sm[];
    float* Ws = sm;            // 16384 floats
    float* Xs = sm + 16384;    // 8192 floats
    const int tid = threadIdx.x;
    const int row0 = blockIdx.x * 64;

    const float4* WT4 = (const float4*)WT;
    float4* Ws4 = (float4*)Ws;
    #pragma unroll
    for (int i = tid; i < 4096; i += 256) Ws4[i] = WT4[i];

    const int rows = min(64, M - row0);
    const int n4 = rows * 32;
    const float4* X4 = (const float4*)(X + (size_t)row0 * 128);
    float4* Xs4 = (float4*)Xs;
    #pragma unroll
    for (int i = tid; i < 2048; i += 256)
        Xs4[i] = (i < n4) ? X4[i] : make_float4(0.f, 0.f, 0.f, 0.f);
    __syncthreads();

    const int tx = tid & 31;   // col group: cols tx*4 .. tx*4+3
    const int ty = tid >> 5;   // row group: rows ty*8 .. ty*8+7

    float acc[8][4];
    #pragma unroll
    for (int i = 0; i < 8; i++)
        #pragma unroll
        for (int j = 0; j < 4; j++) acc[i][j] = 0.f;

    #pragma unroll 4
    for (int k4 = 0; k4 < 32; k4++) {
        float4 w[4];
        #pragma unroll
        for (int kk = 0; kk < 4; kk++)
            w[kk] = *(const float4*)&Ws[(k4 * 4 + kk) * 128 + tx * 4];
        #pragma unroll
        for (int i = 0; i < 8; i++) {
            float4 xv = *(const float4*)&Xs[(ty * 8 + i) * 128 + k4 * 4];
            acc[i][0] += xv.x * w[0].x + xv.y * w[1].x + xv.z * w[2].x + xv.w * w[3].x;
            acc[i][1] += xv.x * w[0].y + xv.y * w[1].y + xv.z * w[2].y + xv.w * w[3].y;
            acc[i][2] += xv.x * w[0].z + xv.y * w[1].z + xv.z * w[2].z + xv.w * w[3].z;
            acc[i][3] += xv.x * w[0].w + xv.y * w[1].w + xv.z * w[2].w + xv.w * w[3].w;
        }
    }

    #pragma unroll
    for (int i = 0; i < 8; i++) {
        int r = row0 + ty * 8 + i;
        if (r < M)
            *(float4*)&Y[(size_t)r * 128 + tx * 4] =
                make_float4(acc[i][0], acc[i][1], acc[i][2], acc[i][3]);
    }
}

// ---------------- edge MLP (factored) + degree accumulation ----------------
// warp per edge: h = relu(A[src] + B[dst] + b_p1); ew = sigmoid(h . w_p2 + b_p2)
__global__ void edge_kernel(const float* __restrict__ b_p1,
                            const float* __restrict__ W_p2,
                            const float* __restrict__ b_p2) {
    int e = (blockIdx.x * blockDim.x + threadIdx.x) >> 5;
    int lane = threadIdx.x & 31;
    if (e >= EE) return;
    int s = g_src[e];
    int d = g_dst[e];
    float2 a  = *(const float2*)&g_AB[(size_t)s * 128 + lane * 2];
    float2 b  = *(const float2*)&g_AB[(size_t)d * 128 + 64 + lane * 2];
    float2 bp = *(const float2*)&b_p1[lane * 2];
    float2 w2 = *(const float2*)&W_p2[lane * 2];
    float h0 = fmaxf(a.x + b.x + bp.x, 0.f);
    float h1 = fmaxf(a.y + b.y + bp.y, 0.f);
    float p = h0 * w2.x + h1 * w2.y;
    #pragma unroll
    for (int o = 16; o; o >>= 1) p += __shfl_xor_sync(0xffffffffu, p, o);
    if (lane == 0) {
        float v = 1.f / (1.f + expf(-(p + b_p2[0])));
        g_ew[e] = v;
        atomicAdd(&g_deg[d], v);
    }
}

__global__ void dinv_kernel() {
    int i = blockIdx.x * blockDim.x + threadIdx.x;
    if (i < NN) g_dinv[i] = rsqrtf(g_deg[i]);  // deg >= 1 always (self-loop)
}

// ---------------- conv init: agg = bias + dinv^2 * xl (self-loop term) ------
__global__ void conv_init(const float* __restrict__ bias) {
    int idx = blockIdx.x * blockDim.x + threadIdx.x;  // over NN*32 float4s
    if (idx >= NN * 32) return;
    int i = idx >> 5;
    int kq = idx & 31;
    float di = g_dinv[i];
    float c = di * di;
    float4 xv = ((const float4*)g_xl)[idx];
    float4 b4 = *(const float4*)&bias[kq * 4];
    float4 r;
    r.x = b4.x + c * xv.x;
    r.y = b4.y + c * xv.y;
    r.z = b4.z + c * xv.z;
    r.w = b4.w + c * xv.w;
    ((float4*)g_agg)[idx] = r;
}

// ---------------- message scatter: agg[dst] += norm * xl[src] ----------------
__global__ void scatter_kernel() {
    int e = (blockIdx.x * blockDim.x + threadIdx.x) >> 5;
    int lane = threadIdx.x & 31;
    if (e >= EE) return;
    int s = g_src[e];
    int d = g_dst[e];
    float c = g_ew[e] * g_dinv[s] * g_dinv[d];
    float4 xv = *(const float4*)&g_xl[(size_t)s * 128 + lane * 4];
    float4 v = make_float4(c * xv.x, c * xv.y, c * xv.z, c * xv.w);
    atomicAdd((float4*)&g_agg[(size_t)d * 128 + lane * 4], v);
}

__global__ void relu_kernel() {
    int idx = blockIdx.x * blockDim.x + threadIdx.x;
    if (idx >= NN * 32) return;
    float4 v = ((const float4*)g_agg)[idx];
    v.x = fmaxf(v.x, 0.f); v.y = fmaxf(v.y, 0.f);
    v.z = fmaxf(v.z, 0.f); v.w = fmaxf(v.w, 0.f);
    ((float4*)g_x1)[idx] = v;
}

// ---------------- final: sigmoid(x2 @ W_lin^T + b_lin) ----------------
__global__ void final_kernel(const float* __restrict__ W_lin,
                             const float* __restrict__ b_lin,
                             float* __restrict__ out) {
    int i = (blockIdx.x * blockDim.x + threadIdx.x) >> 5;
    int lane = threadIdx.x & 31;
    if (i >= NN) return;
    float4 xv = *(const float4*)&g_x1[(size_t)i * 128 + lane * 4];
    float4 w0 = *(const float4*)&W_lin[lane * 4];
    float4 w1 = *(const float4*)&W_lin[128 + lane * 4];
    float p0 = xv.x * w0.x + xv.y * w0.y + xv.z * w0.z + xv.w * w0.w;
    float p1 = xv.x * w1.x + xv.y * w1.y + xv.z * w1.z + xv.w * w1.w;
    #pragma unroll
    for (int o = 16; o; o >>= 1) {
        p0 += __shfl_xor_sync(0xffffffffu, p0, o);
        p1 += __shfl_xor_sync(0xffffffffu, p1, o);
    }
    if (lane == 0) {
        out[2 * i + 0] = 1.f / (1.f + expf(-(p0 + b_lin[0])));
        out[2 * i + 1] = 1.f / (1.f + expf(-(p1 + b_lin[1])));
    }
}

// ---------------- host ----------------
extern "C" void kernel_launch(void* const* d_in, const int* in_sizes, int n_in,
                              void* d_out, int out_size) {
    const float* x     = (const float*)d_in[0];
    const int*   ei    = (const int*)d_in[1];   // int32 or int64 raw words
    const float* W_p1  = (const float*)d_in[2];
    const float* b_p1  = (const float*)d_in[3];
    const float* W_p2  = (const float*)d_in[4];
    const float* b_p2  = (const float*)d_in[5];
    const float* W1    = (const float*)d_in[6];
    const float* b1    = (const float*)d_in[7];
    const float* W2    = (const float*)d_in[8];
    const float* b2    = (const float*)d_in[9];
    const float* W_lin = (const float*)d_in[10];
    const float* b_lin = (const float*)d_in[11];
    float* out = (float*)d_out;

    void *pAB, *pXL, *pX1, *pWTp, *pWT1, *pWT2;
    cudaGetSymbolAddress(&pAB,  g_AB);
    cudaGetSymbolAddress(&pXL,  g_xl);
    cudaGetSymbolAddress(&pX1,  g_x1);
    cudaGetSymbolAddress(&pWTp, g_WTp);
    cudaGetSymbolAddress(&pWT1, g_WT1);
    cudaGetSymbolAddress(&pWT2, g_WT2);

    const int GEMM_SMEM = (16384 + 8192) * 4;  // 96KB
    cudaFuncSetAttribute(gemm128, cudaFuncAttributeMaxDynamicSharedMemorySize, GEMM_SMEM);

    const int gemm_blocks = (NN + 63) / 64;           // 782
    const int edge_blocks = (EE * 32 + 255) / 256;    // warp per edge
    const int e_blocks    = (EE + 255) / 256;
    const int n_blocks    = (NN + 255) / 256;
    const int nf4_blocks  = (NN * 32 + 255) / 256;

    convert_edges<<<e_blocks, 256>>>(ei);
    prep_weights<<<1, 256>>>(W_p1, W1, W2);
    init_deg<<<n_blocks, 256>>>();

    // edge MLP factorized table: AB = x @ [Wp1a^T | Wp1b^T]
    gemm128<<<gemm_blocks, 256, GEMM_SMEM>>>(x, (const float*)pWTp, (float*)pAB, NN);
    edge_kernel<<<edge_blocks, 256>>>(b_p1, W_p2, b_p2);
    dinv_kernel<<<n_blocks, 256>>>();

    // conv1
    gemm128<<<gemm_blocks, 256, GEMM_SMEM>>>(x, (const float*)pWT1, (float*)pXL, NN);
    conv_init<<<nf4_blocks, 256>>>(b1);
    scatter_kernel<<<edge_blocks, 256>>>();
    relu_kernel<<<nf4_blocks, 256>>>();

    // conv2
    gemm128<<<gemm_blocks, 256, GEMM_SMEM>>>((const float*)pX1, (const float*)pWT2, (float*)pXL, NN);
    conv_init<<<nf4_blocks, 256>>>(b2);
    scatter_kernel<<<edge_blocks, 256>>>();
    relu_kernel<<<nf4_blocks, 256>>>();

    // output head
    final_kernel<<<nf4_blocks, 256>>>(W_lin, b_lin, out);
}

// round 3
// speedup vs baseline: 1.0894x; 1.0894x over previous
#include <cuda_runtime.h>
#include <cuda_bf16.h>

#define NN 50000
#define EE 600000
#define NPART 196   // ceil(NN/256)

// ---------------- device scratch ----------------
__device__ __align__(16) float g_AB[NN * 128];
__device__ __align__(16) float g_ew[EE];
__device__ __align__(16) float g_dinv[NN];
__device__ __align__(16) float g_xl[NN * 128];
__device__ __align__(16) float g_x1[NN * 128];
__device__ __align__(16) float g_WTp[128 * 128];
__device__ __align__(16) float g_WT1[128 * 128];
__device__ __align__(16) float g_WT2[128 * 128];
__device__ __align__(16) int   g_src[EE];
__device__ __align__(16) int   g_dst[EE];
__device__ __align__(16) int   g_cnt[NN];
__device__ __align__(16) int   g_part[256];
__device__ __align__(16) int   g_row[NN + 1];
__device__ __align__(16) int   g_cur[NN];
__device__ __align__(16) int   g_csrc[EE];   // CSR: src per slot
__device__ __align__(16) int   g_cdst[EE];   // CSR: dst per slot
__device__ __align__(16) float g_cw[EE];     // CSR: coef per slot

__global__ void zero_cnt() {
    int i = blockIdx.x * blockDim.x + threadIdx.x;
    if (i < NN) g_cnt[i] = 0;
}

// ---------------- edge conversion (dtype-robust) + dst histogram ----------------
__global__ void convert_edges(const int* __restrict__ raw) {
    bool is64 = true;
    #pragma unroll
    for (int i = 1; i < 128; i += 2)
        if (raw[i] != 0) { is64 = false; break; }
    int e = blockIdx.x * blockDim.x + threadIdx.x;
    if (e >= EE) return;
    int s, d;
    if (is64) { s = raw[2 * e];  d = raw[2 * (EE + e)]; }
    else      { s = raw[e];      d = raw[EE + e]; }
    g_src[e] = s;
    g_dst[e] = d;
    atomicAdd(&g_cnt[d], 1);
}

// ---------------- 3-kernel exclusive scan of g_cnt -> g_row, g_cur ----------------
__global__ void scan_part() {
    __shared__ int sm[256];
    int tid = threadIdx.x;
    int i = blockIdx.x * 256 + tid;
    sm[tid] = (i < NN) ? g_cnt[i] : 0;
    __syncthreads();
    for (int o = 128; o; o >>= 1) {
        if (tid < o) sm[tid] += sm[tid + o];
        __syncthreads();
    }
    if (tid == 0) g_part[blockIdx.x] = sm[0];
}

__global__ void scan_tops() {
    __shared__ int sm[256];
    int tid = threadIdx.x;
    int v = (tid < NPART) ? g_part[tid] : 0;
    sm[tid] = v;
    __syncthreads();
    for (int o = 1; o < 256; o <<= 1) {
        int t = sm[tid] + ((tid >= o) ? sm[tid - o] : 0);
        __syncthreads();
        sm[tid] = t;
        __syncthreads();
    }
    if (tid < NPART) g_part[tid] = sm[tid] - v;  // exclusive
}

__global__ void scan_final() {
    __shared__ int sm[256];
    int tid = threadIdx.x;
    int i = blockIdx.x * 256 + tid;
    int v = (i < NN) ? g_cnt[i] : 0;
    sm[tid] = v;
    __syncthreads();
    for (int o = 1; o < 256; o <<= 1) {
        int t = sm[tid] + ((tid >= o) ? sm[tid - o] : 0);
        __syncthreads();
        sm[tid] = t;
        __syncthreads();
    }
    if (i < NN) {
        int excl = sm[tid] - v + g_part[blockIdx.x];
        g_row[i] = excl;
        g_cur[i] = excl;
    }
    if (i == 0) g_row[NN] = EE;
}

// ---------------- weight prep: k-major 128x128 ----------------
__global__ void prep_weights(const float* __restrict__ W_p1,
                             const float* __restrict__ W1,
                             const float* __restrict__ W2) {
    for (int idx = threadIdx.x; idx < 128 * 128; idx += blockDim.x) {
        int k = idx >> 7;
        int j = idx & 127;
        g_WT1[idx] = W1[j * 128 + k];
        g_WT2[idx] = W2[j * 128 + k];
        g_WTp[idx] = (j < 64) ? W_p1[j * 256 + k] : W_p1[(j - 64) * 256 + 128 + k];
    }
}

// ---------------- persistent register-tiled SGEMM ----------------
// Y[M,128] = X[M,128] @ WT (k-major). Grid-stride over 64-row tiles;
// weights loaded into smem once per block.
__global__ void gemm128(const float* __restrict__ X, const float* __restrict__ WT,
                        float* __restrict__ Y, int M) {
    extern __shared__ float sm[];
    float* Ws = sm;            // 16384 floats (64KB)
    float* Xs = sm + 16384;    // 8192 floats (32KB)
    const int tid = threadIdx.x;

    const float4* WT4 = (const float4*)WT;
    float4* Ws4 = (float4*)Ws;
    #pragma unroll
    for (int i = tid; i < 4096; i += 256) Ws4[i] = WT4[i];

    const int tx = tid & 31;
    const int ty = tid >> 5;
    const int ntiles = (M + 63) >> 6;

    for (int tile = blockIdx.x; tile < ntiles; tile += gridDim.x) {
        const int row0 = tile * 64;
        __syncthreads();  // Ws ready / previous compute done
        const int rows = min(64, M - row0);
        const int n4 = rows * 32;
        const float4* X4 = (const float4*)(X + (size_t)row0 * 128);
        float4* Xs4 = (float4*)Xs;
        #pragma unroll
        for (int i = tid; i < 2048; i += 256)
            Xs4[i] = (i < n4) ? X4[i] : make_float4(0.f, 0.f, 0.f, 0.f);
        __syncthreads();

        float acc[8][4];
        #pragma unroll
        for (int i = 0; i < 8; i++)
            #pragma unroll
            for (int j = 0; j < 4; j++) acc[i][j] = 0.f;

        #pragma unroll 4
        for (int k4 = 0; k4 < 32; k4++) {
            float4 w[4];
            #pragma unroll
            for (int kk = 0; kk < 4; kk++)
                w[kk] = *(const float4*)&Ws[(k4 * 4 + kk) * 128 + tx * 4];
            #pragma unroll
            for (int i = 0; i < 8; i++) {
                float4 xv = *(const float4*)&Xs[(ty * 8 + i) * 128 + k4 * 4];
                acc[i][0] += xv.x * w[0].x + xv.y * w[1].x + xv.z * w[2].x + xv.w * w[3].x;
                acc[i][1] += xv.x * w[0].y + xv.y * w[1].y + xv.z * w[2].y + xv.w * w[3].y;
                acc[i][2] += xv.x * w[0].z + xv.y * w[1].z + xv.z * w[2].z + xv.w * w[3].z;
                acc[i][3] += xv.x * w[0].w + xv.y * w[1].w + xv.z * w[2].w + xv.w * w[3].w;
            }
        }

        #pragma unroll
        for (int i = 0; i < 8; i++) {
            int r = row0 + ty * 8 + i;
            if (r < M)
                *(float4*)&Y[(size_t)r * 128 + tx * 4] =
                    make_float4(acc[i][0], acc[i][1], acc[i][2], acc[i][3]);
        }
    }
}

// ---------------- edge MLP (factored): ew = sigmoid(relu(A[s]+B[d]+b).w2 + b2) --
__global__ void edge_kernel(const float* __restrict__ b_p1,
                            const float* __restrict__ W_p2,
                            const float* __restrict__ b_p2) {
    int e = (blockIdx.x * blockDim.x + threadIdx.x) >> 5;
    int lane = threadIdx.x & 31;
    if (e >= EE) return;
    int s = g_src[e];
    int d = g_dst[e];
    float2 a  = *(const float2*)&g_AB[(size_t)s * 128 + lane * 2];
    float2 b  = *(const float2*)&g_AB[(size_t)d * 128 + 64 + lane * 2];
    float2 bp = *(const float2*)&b_p1[lane * 2];
    float2 w2 = *(const float2*)&W_p2[lane * 2];
    float h0 = fmaxf(a.x + b.x + bp.x, 0.f);
    float h1 = fmaxf(a.y + b.y + bp.y, 0.f);
    float p = h0 * w2.x + h1 * w2.y;
    #pragma unroll
    for (int o = 16; o; o >>= 1) p += __shfl_xor_sync(0xffffffffu, p, o);
    if (lane == 0)
        g_ew[e] = 1.f / (1.f + expf(-(p + b_p2[0])));
}

// ---------------- CSR fill ----------------
__global__ void fill_csr() {
    int e = blockIdx.x * blockDim.x + threadIdx.x;
    if (e >= EE) return;
    int d = g_dst[e];
    int slot = atomicAdd(&g_cur[d], 1);
    g_csrc[slot] = g_src[e];
    g_cdst[slot] = d;
    g_cw[slot]   = g_ew[e];
}

// ---------------- deg -> dinv (segmented sum over CSR row) ----------------
__global__ void deg_kernel() {
    int i = blockIdx.x * blockDim.x + threadIdx.x;
    if (i >= NN) return;
    int e0 = g_row[i], e1 = g_row[i + 1];
    float s = 1.0f;  // self loop
    for (int j = e0; j < e1; j++) s += g_cw[j];
    g_dinv[i] = rsqrtf(s);
}

// ---------------- per-slot coefficient: cw *= dinv[s]*dinv[d] ----------------
__global__ void coef_kernel() {
    int j = blockIdx.x * blockDim.x + threadIdx.x;
    if (j >= EE) return;
    g_cw[j] *= g_dinv[g_csrc[j]] * g_dinv[g_cdst[j]];
}

// ---------------- conv (gather form) + relu ----------------
// block = 128 threads (one feature each), one node per block
__global__ void conv_relu(const float* __restrict__ bias) {
    int n = blockIdx.x;
    int f = threadIdx.x;
    float di = g_dinv[n];
    float acc = bias[f] + di * di * g_xl[(size_t)n * 128 + f];
    int e0 = g_row[n], e1 = g_row[n + 1];
    for (int j = e0; j < e1; j++) {
        int s = g_csrc[j];         // uniform across block
        float c = g_cw[j];         // uniform
        acc += c * g_xl[(size_t)s * 128 + f];
    }
    g_x1[(size_t)n * 128 + f] = fmaxf(acc, 0.f);
}

// ---------------- conv2 + fused head: sigmoid(relu(agg) @ W_lin^T + b_lin) -----
__global__ void conv_head(const float* __restrict__ bias,
                          const float* __restrict__ W_lin,
                          const float* __restrict__ b_lin,
                          float* __restrict__ out) {
    int n = blockIdx.x;
    int f = threadIdx.x;
    float di = g_dinv[n];
    float acc = bias[f] + di * di * g_xl[(size_t)n * 128 + f];
    int e0 = g_row[n], e1 = g_row[n + 1];
    for (int j = e0; j < e1; j++) {
        int s = g_csrc[j];
        float c = g_cw[j];
        acc += c * g_xl[(size_t)s * 128 + f];
    }
    float v = fmaxf(acc, 0.f);
    __shared__ float2 red[128];
    red[f] = make_float2(v * W_lin[f], v * W_lin[128 + f]);
    __syncthreads();
    #pragma unroll
    for (int o = 64; o; o >>= 1) {
        if (f < o) {
            red[f].x += red[f + o].x;
            red[f].y += red[f + o].y;
        }
        __syncthreads();
    }
    if (f == 0) {
        out[2 * n + 0] = 1.f / (1.f + expf(-(red[0].x + b_lin[0])));
        out[2 * n + 1] = 1.f / (1.f + expf(-(red[0].y + b_lin[1])));
    }
}

// ---------------- host ----------------
extern "C" void kernel_launch(void* const* d_in, const int* in_sizes, int n_in,
                              void* d_out, int out_size) {
    const float* x     = (const float*)d_in[0];
    const int*   ei    = (const int*)d_in[1];
    const float* W_p1  = (const float*)d_in[2];
    const float* b_p1  = (const float*)d_in[3];
    const float* W_p2  = (const float*)d_in[4];
    const float* b_p2  = (const float*)d_in[5];
    const float* W1    = (const float*)d_in[6];
    const float* b1    = (const float*)d_in[7];
    const float* W2    = (const float*)d_in[8];
    const float* b2    = (const float*)d_in[9];
    const float* W_lin = (const float*)d_in[10];
    const float* b_lin = (const float*)d_in[11];
    float* out = (float*)d_out;

    void *pAB, *pXL, *pX1, *pWTp, *pWT1, *pWT2;
    cudaGetSymbolAddress(&pAB,  g_AB);
    cudaGetSymbolAddress(&pXL,  g_xl);
    cudaGetSymbolAddress(&pX1,  g_x1);
    cudaGetSymbolAddress(&pWTp, g_WTp);
    cudaGetSymbolAddress(&pWT1, g_WT1);
    cudaGetSymbolAddress(&pWT2, g_WT2);

    const int GEMM_SMEM = (16384 + 8192) * 4;  // 96KB
    cudaFuncSetAttribute(gemm128, cudaFuncAttributeMaxDynamicSharedMemorySize, GEMM_SMEM);

    const int GEMM_GRID = 296;                        // 2 blocks/SM persistent
    const int edge_blocks = (EE * 32 + 255) / 256;    // warp per edge
    const int e_blocks    = (EE + 255) / 256;
    const int n_blocks    = (NN + 255) / 256;

    // CSR build
    zero_cnt<<<n_blocks, 256>>>();
    convert_edges<<<e_blocks, 256>>>(ei);
    scan_part<<<NPART, 256>>>();
    scan_tops<<<1, 256>>>();
    scan_final<<<NPART, 256>>>();

    prep_weights<<<1, 256>>>(W_p1, W1, W2);

    // edge MLP
    gemm128<<<GEMM_GRID, 256, GEMM_SMEM>>>(x, (const float*)pWTp, (float*)pAB, NN);
    edge_kernel<<<edge_blocks, 256>>>(b_p1, W_p2, b_p2);
    fill_csr<<<e_blocks, 256>>>();
    deg_kernel<<<n_blocks, 256>>>();
    coef_kernel<<<e_blocks, 256>>>();

    // conv1
    gemm128<<<GEMM_GRID, 256, GEMM_SMEM>>>(x, (const float*)pWT1, (float*)pXL, NN);
    conv_relu<<<NN, 128>>>(b1);

    // conv2 + head
    gemm128<<<GEMM_GRID, 256, GEMM_SMEM>>>((const float*)pX1, (const float*)pWT2, (float*)pXL, NN);
    conv_head<<<NN, 128>>>(b2, W_lin, b_lin, out);
}